// round 10
// baseline (speedup 1.0000x reference)
#include <cuda_runtime.h>
#include <math.h>
#include <stdint.h>
#include <stddef.h>

#define NTOK 16384
#define CD   128
#define NB   65536
#define BMR  1024

static constexpr size_t SZ = (size_t)NB * CD;   // 8388608
static constexpr size_t OFF_XA0 = 0;
static constexpr size_t OFF_XA1 = SZ;
static constexpr size_t OFF_Q   = 2*SZ;          // 2 slices
static constexpr size_t OFF_PART= 4*SZ;          // 64*1024*128 == SZ
static constexpr size_t OFF_WC  = 5*SZ;
static constexpr size_t OFF_XILN= OFF_WC  + (size_t)CD*8192;
static constexpr size_t OFF_KVB = OFF_XILN+ (size_t)2*BMR*CD;
static constexpr size_t OFF_KH  = OFF_KVB + (size_t)2*BMR*2*CD;
static constexpr size_t OFF_VHT = OFF_KH  + (size_t)16*256*64;
static constexpr size_t OFF_SC  = OFF_VHT + (size_t)16*256*64;   // (unused now)
static constexpr size_t OFF_HB  = OFF_SC  + 8*SZ;
static constexpr size_t OFF_SB  = OFF_HB  + 2*SZ;
static constexpr size_t OFF_QKV = OFF_SB  + 2*SZ;
static constexpr size_t OFF_K1  = OFF_QKV + 3*SZ;
static constexpr size_t OFF_V1  = OFF_K1  + SZ;
static constexpr size_t OFF_OB  = OFF_V1  + SZ;
static constexpr size_t OFF_N0  = OFF_OB  + SZ;
static constexpr size_t OFF_N1  = OFF_N0  + SZ;
static constexpr size_t OFF_CST = OFF_N1  + SZ;
static constexpr size_t POOL_SZ = OFF_CST + 256;

__device__ float g_pool[POOL_SZ];

__device__ __forceinline__ float geluf(float x) {
    return 0.5f * x * (1.0f + erff(x * 0.70710678118654752f));
}
__device__ __forceinline__ uint32_t f2tf32(float x) {
    uint32_t r; asm("cvt.rna.tf32.f32 %0, %1;" : "=r"(r) : "f"(x)); return r;
}
__device__ __forceinline__ uint32_t u2tf32(uint32_t u) {
    return f2tf32(__uint_as_float(u));
}
__device__ __forceinline__ void mma8(float* c, const uint32_t* a, const uint32_t* b) {
    asm volatile("mma.sync.aligned.m16n8k8.row.col.f32.tf32.tf32.f32 "
        "{%0,%1,%2,%3}, {%4,%5,%6,%7}, {%8,%9}, {%0,%1,%2,%3};"
        : "+f"(c[0]), "+f"(c[1]), "+f"(c[2]), "+f"(c[3])
        : "r"(a[0]), "r"(a[1]), "r"(a[2]), "r"(a[3]), "r"(b[0]), "r"(b[1]));
}
__device__ __forceinline__ void ldsm4(uint32_t* r, uint32_t addr) {
    asm volatile("ldmatrix.sync.aligned.m8n8.x4.shared.b16 {%0,%1,%2,%3}, [%4];"
        : "=r"(r[0]), "=r"(r[1]), "=r"(r[2]), "=r"(r[3]) : "r"(addr));
}
__device__ __forceinline__ void ldsm2(uint32_t* r, uint32_t addr) {
    asm volatile("ldmatrix.sync.aligned.m8n8.x2.shared.b16 {%0,%1}, [%2];"
        : "=r"(r[0]), "=r"(r[1]) : "r"(addr));
}
__device__ __forceinline__ void cpa16(uint32_t d, const void* s) {
    asm volatile("cp.async.cg.shared.global [%0], [%1], 16;" :: "r"(d), "l"(s));
}
__device__ __forceinline__ void cpcommit() { asm volatile("cp.async.commit_group;"); }
template<int N> __device__ __forceinline__ void cpwait() {
    asm volatile("cp.async.wait_group %0;" :: "n"(N));
}

// ---------------------------------------------------------------------------
// tf32 GEMM template (unchanged from R7, minus unused instantiations).
// ---------------------------------------------------------------------------
template<int BM, int BN, int KTILES, int AMODE, int EPI, int SMAX>
__global__ void __launch_bounds__(256, 2) tgemm_k(
    const float* __restrict__ A0, const float* __restrict__ A1,
    const float* __restrict__ W,  const float* __restrict__ bias,
    const float* __restrict__ res, float* __restrict__ out,
    int lda, int ldw, int ldo, size_t zsa, size_t zso)
{
    constexpr int PAD = 36;
    constexpr int colWarps = BN / 32;
    constexpr int rowWarps = 8 / colWarps;
    constexpr int WM = BM / rowWarps;
    constexpr int MT = WM / 16;
    constexpr int ACH = BM / 32;
    constexpr int WCH = BN / 32;
    constexpr int STG = (BM + BN) * PAD;

    extern __shared__ float smem[];

    const int tid = threadIdx.x;
    const int w = tid >> 5, lane = tid & 31, g = lane >> 2, t = lane & 3;
    const int warpRow = w / colWarps, warpCol = w % colWarps;
    const int row0 = blockIdx.x * BM, col0 = blockIdx.y * BN;
    const int z = blockIdx.z;

    const float* Ap = A0 + z * zsa;
    const float* Aa = A0; const float* Ab = A1;
    const float* Wp = W;
    const float* Xs = A0;
    float* op = out + z * zso;
    int koff0 = 0;
    if (AMODE == 5) {
        Ap = z ? A1 : A0;
    } else if (AMODE == 6) {
        Aa = z ? A1 : A0; Ab = z ? A0 : A1;
    } else if (AMODE == 7) {
        Xs = (z >= 32) ? A1 : A0;
        koff0 = (z & 31) * (KTILES * 32);
    }

    const uint32_t smemB = (uint32_t)__cvta_generic_to_shared(smem);

    auto copy_tile = [&](int kt, int stage) {
        const int koff = koff0 + kt * 32;
        float* AsS = smem + stage * STG;
        const uint32_t aB = smemB + stage * STG * 4;
        const uint32_t wB = aB + BM * PAD * 4;
        #pragma unroll
        for (int i = 0; i < ACH; ++i) {
            const int fidx = i * 256 + tid;
            const int arow = fidx >> 3, kq = (fidx & 7) * 4;
            const int kg = koff + kq;
            if (AMODE == 2) {
                float4 a = *(const float4*)(A0 + (size_t)(row0 + arow) * lda + kg);
                float4 b = *(const float4*)(A1 + (size_t)(row0 + arow) * lda + kg);
                *(float4*)(AsS + arow * PAD + kq) = make_float4(a.x*b.x, a.y*b.y, a.z*b.z, a.w*b.w);
            } else {
                const float* src;
                if (AMODE == 6) {
                    src = (kg < 128) ? (Aa + (size_t)(row0 + arow) * 128 + kg)
                                     : (Ab + (size_t)(row0 + arow) * 128 + (kg - 128));
                } else if (AMODE == 7) {
                    const int gr = row0 + arow;
                    const int b_ = gr >> 8, p = gr & 255, ph = p >> 4, pw = p & 15;
                    const int ij = kg >> 7, c = kg & 127;
                    src = Xs + ((size_t)(b_ * 16384 + (ph*8 + (ij>>3)) * 128 + pw*8 + (ij&7))) * 128 + c;
                } else {
                    src = Ap + (size_t)(row0 + arow) * lda + kg;
                }
                cpa16(aB + (uint32_t)(arow * PAD + kq) * 4, src);
            }
        }
        #pragma unroll
        for (int i = 0; i < WCH; ++i) {
            const int fidx = i * 256 + tid;
            const int wrow = fidx >> 3, kq = (fidx & 7) * 4;
            cpa16(wB + (uint32_t)(wrow * PAD + kq) * 4,
                  Wp + (size_t)(col0 + wrow) * ldw + koff + kq);
        }
        cpcommit();
    };

    const int laneRowA = ((lane >> 3) & 1) * 8 + (lane & 7);
    const int laneKA   = (lane >> 4) * 4;
    const int laneRowB = lane & 7;
    const int laneKB   = ((lane >> 3) & 1) * 4;

    float acc[MT][4][4] = {};

    copy_tile(0, 0);
    for (int kt = 0; kt < KTILES; ++kt) {
        if (kt + 1 < KTILES) { copy_tile(kt + 1, (kt + 1) & 1); cpwait<1>(); }
        else cpwait<0>();
        __syncthreads();
        const uint32_t aB = smemB + (kt & 1) * STG * 4;
        const uint32_t wB = aB + BM * PAD * 4;
        #pragma unroll
        for (int k0 = 0; k0 < 32; k0 += 8) {
            uint32_t bf[4][2];
            #pragma unroll
            for (int nt = 0; nt < 4; ++nt) {
                ldsm2(bf[nt], wB + 4u * ((warpCol*32 + nt*8 + laneRowB) * PAD + laneKB + k0));
                bf[nt][0] = u2tf32(bf[nt][0]); bf[nt][1] = u2tf32(bf[nt][1]);
            }
            #pragma unroll
            for (int mt = 0; mt < MT; ++mt) {
                uint32_t af[4];
                ldsm4(af, aB + 4u * ((warpRow*WM + mt*16 + laneRowA) * PAD + laneKA + k0));
                af[0]=u2tf32(af[0]); af[1]=u2tf32(af[1]); af[2]=u2tf32(af[2]); af[3]=u2tf32(af[3]);
                #pragma unroll
                for (int nt = 0; nt < 4; ++nt) mma8(acc[mt][nt], af, bf[nt]);
            }
        }
        __syncthreads();
    }

    if (EPI == 0 || EPI == 1 || EPI == 2) {
        #pragma unroll
        for (int nt = 0; nt < 4; ++nt) {
            const int cc = col0 + warpCol * 32 + nt * 8 + 2 * t;
            const float bx = bias[cc], by = bias[cc + 1];
            #pragma unroll
            for (int mt = 0; mt < MT; ++mt) {
                acc[mt][nt][0] += bx; acc[mt][nt][1] += by;
                acc[mt][nt][2] += bx; acc[mt][nt][3] += by;
            }
        }
    }

    if (SMAX) {
        float* redbuf = smem;
        float rowmax[MT][2];
        #pragma unroll
        for (int mt = 0; mt < MT; ++mt)
            #pragma unroll
            for (int h = 0; h < 2; ++h) {
                float m = -3.4e38f;
                #pragma unroll
                for (int nt = 0; nt < 4; ++nt)
                    m = fmaxf(m, fmaxf(acc[mt][nt][h*2], acc[mt][nt][h*2+1]));
                m = fmaxf(m, __shfl_xor_sync(0xffffffffu, m, 1));
                m = fmaxf(m, __shfl_xor_sync(0xffffffffu, m, 2));
                const int rl = warpRow * WM + mt * 16 + g + h * 8;
                if (t == 0) redbuf[rl * colWarps + warpCol] = m;
                rowmax[mt][h] = m;
            }
        __syncthreads();
        #pragma unroll
        for (int mt = 0; mt < MT; ++mt)
            #pragma unroll
            for (int h = 0; h < 2; ++h) {
                const int rl = warpRow * WM + mt * 16 + g + h * 8;
                float m = -3.4e38f;
                #pragma unroll
                for (int cw = 0; cw < colWarps; ++cw)
                    m = fmaxf(m, redbuf[rl * colWarps + cw]);
                rowmax[mt][h] = m;
            }
        __syncthreads();
        #pragma unroll
        for (int mt = 0; mt < MT; ++mt)
            #pragma unroll
            for (int h = 0; h < 2; ++h) {
                float s = 0.f;
                #pragma unroll
                for (int nt = 0; nt < 4; ++nt) {
                    acc[mt][nt][h*2]   = __expf(acc[mt][nt][h*2]   - rowmax[mt][h]);
                    acc[mt][nt][h*2+1] = __expf(acc[mt][nt][h*2+1] - rowmax[mt][h]);
                    s += acc[mt][nt][h*2] + acc[mt][nt][h*2+1];
                }
                s += __shfl_xor_sync(0xffffffffu, s, 1);
                s += __shfl_xor_sync(0xffffffffu, s, 2);
                const int rl = warpRow * WM + mt * 16 + g + h * 8;
                if (t == 0) redbuf[rl * colWarps + warpCol] = s;
            }
        __syncthreads();
        #pragma unroll
        for (int mt = 0; mt < MT; ++mt)
            #pragma unroll
            for (int h = 0; h < 2; ++h) {
                const int rl = warpRow * WM + mt * 16 + g + h * 8;
                float s = 0.f;
                #pragma unroll
                for (int cw = 0; cw < colWarps; ++cw) s += redbuf[rl * colWarps + cw];
                const float inv = 1.0f / s;
                #pragma unroll
                for (int nt = 0; nt < 4; ++nt) {
                    acc[mt][nt][h*2] *= inv; acc[mt][nt][h*2+1] *= inv;
                }
            }
    }

    #pragma unroll
    for (int mt = 0; mt < MT; ++mt) {
        const int r = row0 + warpRow * WM + mt * 16 + g;
        #pragma unroll
        for (int nt = 0; nt < 4; ++nt) {
            const int cc = col0 + warpCol * 32 + nt * 8 + 2 * t;
            float v0 = acc[mt][nt][0], v1 = acc[mt][nt][1];
            float v2 = acc[mt][nt][2], v3 = acc[mt][nt][3];
            if (EPI == 1) { v0=geluf(v0); v1=geluf(v1); v2=geluf(v2); v3=geluf(v3); }
            if (EPI == 2) {
                float2 r0 = *(const float2*)(res + (size_t)r * ldo + cc);
                float2 r1 = *(const float2*)(res + (size_t)(r + 8) * ldo + cc);
                v0 += r0.x; v1 += r0.y; v2 += r1.x; v3 += r1.y;
            }
            *(float2*)(op + (size_t)r       * ldo + cc) = make_float2(v0, v1);
            *(float2*)(op + (size_t)(r + 8) * ldo + cc) = make_float2(v2, v3);
        }
    }
}

// ---------------------------------------------------------------------------
// Flash SR attention: per CTA, 64 queries x one z=(s,b,h); K,V resident smem.
// Phase1 S=Q@K^T (64x256), full-row softmax, P->smem; Phase2 P@V^T -> XA.
// ---------------------------------------------------------------------------
#define FP_QS 0
#define FP_KS (64*68)
#define FP_VS (FP_KS + 256*68)
#define FP_PS (FP_VS + 64*260)
#define FP_TOT (FP_PS + 64*260)          // 55040 floats = 220160 B

__global__ void __launch_bounds__(256, 1) flashsr_k(
    const float* __restrict__ Qb, const float* __restrict__ KH,
    const float* __restrict__ VHT, float* __restrict__ XAb)
{
    extern __shared__ float smem[];
    const int tid = threadIdx.x;
    const int w = tid >> 5, lane = tid & 31, g = lane >> 2, t = lane & 3;
    const int q0 = blockIdx.x * 64;
    const int z = blockIdx.y;
    const int s = z >> 3, b = (z >> 1) & 3, h = z & 1;

    const float* Qp = Qb + (size_t)s * SZ + (size_t)b * (NTOK * 128) + h * 64;
    const float* Kp = KH + (size_t)z * 16384;
    const float* Vp = VHT + (size_t)z * 16384;
    float* XAp = XAb + (size_t)s * SZ + (size_t)b * (NTOK * 128) + h * 64;

    const uint32_t smemB = (uint32_t)__cvta_generic_to_shared(smem);
    const uint32_t qB = smemB + FP_QS * 4;
    const uint32_t kB = smemB + FP_KS * 4;
    const uint32_t vB = smemB + FP_VS * 4;
    const uint32_t pB = smemB + FP_PS * 4;

    // load Q (64x64), K (256x64), Vt (64x256)
    #pragma unroll
    for (int i = 0; i < 4; ++i) {
        const int fidx = i * 256 + tid;           // 0..1023
        const int r = fidx >> 4, c = (fidx & 15) * 4;
        cpa16(qB + (uint32_t)(r * 68 + c) * 4, Qp + (size_t)(q0 + r) * 128 + c);
    }
    #pragma unroll
    for (int i = 0; i < 16; ++i) {
        const int fidx = i * 256 + tid;           // 0..4095
        const int r = fidx >> 4, c = (fidx & 15) * 4;
        cpa16(kB + (uint32_t)(r * 68 + c) * 4, Kp + (size_t)r * 64 + c);
    }
    #pragma unroll
    for (int i = 0; i < 16; ++i) {
        const int fidx = i * 256 + tid;           // 0..4095
        const int r = fidx >> 6, c = (fidx & 63) * 4;
        cpa16(vB + (uint32_t)(r * 260 + c) * 4, Vp + (size_t)r * 256 + c);
    }
    cpcommit();
    cpwait<0>();
    __syncthreads();

    const int laneRowA = ((lane >> 3) & 1) * 8 + (lane & 7);
    const int laneKA   = (lane >> 4) * 4;
    const int laneRowB = lane & 7;
    const int laneKB   = ((lane >> 3) & 1) * 4;

    // ---- Phase 1: S (64x256), warp w owns cols w*32..w*32+31, MT=4 ----
    float acc[4][4][4] = {};
    #pragma unroll
    for (int k0 = 0; k0 < 64; k0 += 8) {
        uint32_t bf[4][2];
        #pragma unroll
        for (int nt = 0; nt < 4; ++nt) {
            ldsm2(bf[nt], kB + 4u * ((w*32 + nt*8 + laneRowB) * 68 + laneKB + k0));
            bf[nt][0] = u2tf32(bf[nt][0]); bf[nt][1] = u2tf32(bf[nt][1]);
        }
        #pragma unroll
        for (int mt = 0; mt < 4; ++mt) {
            uint32_t af[4];
            ldsm4(af, qB + 4u * ((mt*16 + laneRowA) * 68 + laneKA + k0));
            af[0]=u2tf32(af[0]); af[1]=u2tf32(af[1]); af[2]=u2tf32(af[2]); af[3]=u2tf32(af[3]);
            #pragma unroll
            for (int nt = 0; nt < 4; ++nt) mma8(acc[mt][nt], af, bf[nt]);
        }
    }
    __syncthreads();                      // Qs region free -> redbuf

    // ---- softmax over 256 (rows fully in-block; 8 col-warps) ----
    float* redbuf = smem;                 // 64 rows x 8 warps
    float rowmax[4][2];
    #pragma unroll
    for (int mt = 0; mt < 4; ++mt)
        #pragma unroll
        for (int hh = 0; hh < 2; ++hh) {
            float m = -3.4e38f;
            #pragma unroll
            for (int nt = 0; nt < 4; ++nt)
                m = fmaxf(m, fmaxf(acc[mt][nt][hh*2], acc[mt][nt][hh*2+1]));
            m = fmaxf(m, __shfl_xor_sync(0xffffffffu, m, 1));
            m = fmaxf(m, __shfl_xor_sync(0xffffffffu, m, 2));
            const int rl = mt*16 + g + hh*8;
            if (t == 0) redbuf[rl * 8 + w] = m;
            rowmax[mt][hh] = m;
        }
    __syncthreads();
    #pragma unroll
    for (int mt = 0; mt < 4; ++mt)
        #pragma unroll
        for (int hh = 0; hh < 2; ++hh) {
            const int rl = mt*16 + g + hh*8;
            float m = -3.4e38f;
            #pragma unroll
            for (int cw = 0; cw < 8; ++cw) m = fmaxf(m, redbuf[rl*8 + cw]);
            rowmax[mt][hh] = m;
        }
    __syncthreads();
    #pragma unroll
    for (int mt = 0; mt < 4; ++mt)
        #pragma unroll
        for (int hh = 0; hh < 2; ++hh) {
            float sum = 0.f;
            #pragma unroll
            for (int nt = 0; nt < 4; ++nt) {
                acc[mt][nt][hh*2]   = __expf(acc[mt][nt][hh*2]   - rowmax[mt][hh]);
                acc[mt][nt][hh*2+1] = __expf(acc[mt][nt][hh*2+1] - rowmax[mt][hh]);
                sum += acc[mt][nt][hh*2] + acc[mt][nt][hh*2+1];
            }
            sum += __shfl_xor_sync(0xffffffffu, sum, 1);
            sum += __shfl_xor_sync(0xffffffffu, sum, 2);
            const int rl = mt*16 + g + hh*8;
            if (t == 0) redbuf[rl * 8 + w] = sum;
        }
    __syncthreads();
    float* Ps = smem + FP_PS;
    #pragma unroll
    for (int mt = 0; mt < 4; ++mt)
        #pragma unroll
        for (int hh = 0; hh < 2; ++hh) {
            const int rl = mt*16 + g + hh*8;
            float sum = 0.f;
            #pragma unroll
            for (int cw = 0; cw < 8; ++cw) sum += redbuf[rl*8 + cw];
            const float inv = 1.0f / sum;
            #pragma unroll
            for (int nt = 0; nt < 4; ++nt) {
                const int cc = w*32 + nt*8 + 2*t;
                *(float2*)(Ps + rl * 260 + cc) =
                    make_float2(acc[mt][nt][hh*2] * inv, acc[mt][nt][hh*2+1] * inv);
            }
        }
    __syncthreads();

    // ---- Phase 2: XA (64x64) = P (64x256) @ Vt^T; colWarps=2, WM=16 ----
    const int wr2 = w >> 1, wc2 = w & 1;
    float acc2[4][4] = {};
    #pragma unroll 4
    for (int k0 = 0; k0 < 256; k0 += 8) {
        uint32_t bf[4][2];
        #pragma unroll
        for (int nt = 0; nt < 4; ++nt) {
            ldsm2(bf[nt], vB + 4u * ((wc2*32 + nt*8 + laneRowB) * 260 + laneKB + k0));
            bf[nt][0] = u2tf32(bf[nt][0]); bf[nt][1] = u2tf32(bf[nt][1]);
        }
        uint32_t af[4];
        ldsm4(af, pB + 4u * ((wr2*16 + laneRowA) * 260 + laneKA + k0));
        af[0]=u2tf32(af[0]); af[1]=u2tf32(af[1]); af[2]=u2tf32(af[2]); af[3]=u2tf32(af[3]);
        #pragma unroll
        for (int nt = 0; nt < 4; ++nt) mma8(acc2[nt], af, bf[nt]);
    }
    #pragma unroll
    for (int nt = 0; nt < 4; ++nt) {
        const int cc = wc2*32 + nt*8 + 2*t;
        const int r = q0 + wr2*16 + g;
        *(float2*)(XAp + (size_t)r       * 128 + cc) = make_float2(acc2[nt][0], acc2[nt][1]);
        *(float2*)(XAp + (size_t)(r + 8) * 128 + cc) = make_float2(acc2[nt][2], acc2[nt][3]);
    }
}

// ---------------------------------------------------------------------------
// qkv projection with persistent A tile: out[128 x 384] per block, A read once.
// ---------------------------------------------------------------------------
__global__ void __launch_bounds__(256, 2) qkv_k(
    const float* __restrict__ A, const float* __restrict__ W,
    const float* __restrict__ bias, float* __restrict__ out)
{
    extern __shared__ float smem[];                // As 128x132, Ws 2x(128x36)
    const int tid = threadIdx.x;
    const int w = tid >> 5, lane = tid & 31, g = lane >> 2, t = lane & 3;
    const int warpRow = w >> 2, warpCol = w & 3;   // 2x4 warps
    const int row0 = blockIdx.x * 128;

    const uint32_t smemB = (uint32_t)__cvta_generic_to_shared(smem);
    const uint32_t aB = smemB;
    const uint32_t wS = smemB + 128 * 132 * 4;

    auto copy_w = [&](int j, int stage) {          // j = nl*4 + kt
        const int nl = j >> 2, koff = (j & 3) * 32;
        const uint32_t wB = wS + stage * 128 * 36 * 4;
        #pragma unroll
        for (int i = 0; i < 4; ++i) {
            const int fidx = i * 256 + tid;
            const int wrow = fidx >> 3, kq = (fidx & 7) * 4;
            cpa16(wB + (uint32_t)(wrow * 36 + kq) * 4,
                  W + (size_t)(nl * 128 + wrow) * 128 + koff + kq);
        }
        cpcommit();
    };

    // load A once (128x128)
    #pragma unroll
    for (int i = 0; i < 16; ++i) {
        const int fidx = i * 256 + tid;            // 0..4095
        const int arow = fidx >> 5, kq = (fidx & 31) * 4;
        cpa16(aB + (uint32_t)(arow * 132 + kq) * 4, A + (size_t)(row0 + arow) * 128 + kq);
    }
    copy_w(0, 0);                                  // A + W0 in group 0

    const int laneRowA = ((lane >> 3) & 1) * 8 + (lane & 7);
    const int laneKA   = (lane >> 4) * 4;
    const int laneRowB = lane & 7;
    const int laneKB   = ((lane >> 3) & 1) * 4;

    float acc[4][4][4];
    for (int j = 0; j < 12; ++j) {
        const int kt = j & 3, nl = j >> 2;
        if (kt == 0) {
            #pragma unroll
            for (int mt = 0; mt < 4; ++mt)
                #pragma unroll
                for (int nt = 0; nt < 4; ++nt)
                    #pragma unroll
                    for (int q = 0; q < 4; ++q) acc[mt][nt][q] = 0.f;
        }
        if (j + 1 < 12) { copy_w(j + 1, (j + 1) & 1); cpwait<1>(); }
        else cpwait<0>();
        __syncthreads();
        const uint32_t wB = wS + (j & 1) * 128 * 36 * 4;
        const int koff = kt * 32;
        #pragma unroll
        for (int k0 = 0; k0 < 32; k0 += 8) {
            uint32_t bf[4][2];
            #pragma unroll
            for (int nt = 0; nt < 4; ++nt) {
                ldsm2(bf[nt], wB + 4u * ((warpCol*32 + nt*8 + laneRowB) * 36 + laneKB + k0));
                bf[nt][0] = u2tf32(bf[nt][0]); bf[nt][1] = u2tf32(bf[nt][1]);
            }
            #pragma unroll
            for (int mt = 0; mt < 4; ++mt) {
                uint32_t af[4];
                ldsm4(af, aB + 4u * ((warpRow*64 + mt*16 + laneRowA) * 132 + laneKA + koff + k0));
                af[0]=u2tf32(af[0]); af[1]=u2tf32(af[1]); af[2]=u2tf32(af[2]); af[3]=u2tf32(af[3]);
                #pragma unroll
                for (int nt = 0; nt < 4; ++nt) mma8(acc[mt][nt], af, bf[nt]);
            }
        }
        __syncthreads();
        if (kt == 3) {
            #pragma unroll
            for (int mt = 0; mt < 4; ++mt) {
                const int r = row0 + warpRow*64 + mt*16 + g;
                #pragma unroll
                for (int nt = 0; nt < 4; ++nt) {
                    const int cl = warpCol*32 + nt*8 + 2*t;
                    const int cc = nl * 128 + cl;
                    const float bx = bias[cc], by = bias[cc+1];
                    *(float2*)(out + (size_t)r       * 384 + cc) =
                        make_float2(acc[mt][nt][0] + bx, acc[mt][nt][1] + by);
                    *(float2*)(out + (size_t)(r + 8) * 384 + cc) =
                        make_float2(acc[mt][nt][2] + bx, acc[mt][nt][3] + by);
                }
            }
        }
    }
}

__global__ void wconv_k(const float* __restrict__ w, float* __restrict__ wc)
{
    const int idx = blockIdx.x * blockDim.x + threadIdx.x;
    if (idx >= CD * 8192) return;
    const int o = idx >> 13, k = idx & 8191, ij = k >> 7, c = k & 127;
    wc[idx] = w[(size_t)o * 8192 + c * 64 + ij];
}

__global__ void convred_ln_k(const float* __restrict__ part, const float* __restrict__ sb,
                             const float* __restrict__ g0, const float* __restrict__ b0,
                             const float* __restrict__ g1, const float* __restrict__ b1,
                             float* __restrict__ outp)
{
    const int row = blockIdx.x, c = threadIdx.x;
    const int s = row >> 10, rl = row & 1023;
    const float* g  = s ? g1 : g0;
    const float* be = s ? b1 : b0;
    float v = sb[c];
    #pragma unroll
    for (int zz = 0; zz < 32; ++zz)
        v += part[(size_t)(s*32 + zz) * BMR * CD + (size_t)rl * CD + c];
    __shared__ float red[4], red2[4];
    float sum = v;
    #pragma unroll
    for (int o = 16; o; o >>= 1) sum += __shfl_xor_sync(0xffffffffu, sum, o);
    if ((c & 31) == 0) red[c >> 5] = sum;
    __syncthreads();
    const float mean = (red[0]+red[1]+red[2]+red[3]) * (1.0f/CD);
    const float d = v - mean;
    float s2 = d * d;
    #pragma unroll
    for (int o = 16; o; o >>= 1) s2 += __shfl_xor_sync(0xffffffffu, s2, o);
    if ((c & 31) == 0) red2[c >> 5] = s2;
    __syncthreads();
    const float var = (red2[0]+red2[1]+red2[2]+red2[3]) * (1.0f/CD);
    outp[(size_t)row * CD + c] = d * rsqrtf(var + 1e-5f) * g[c] + be[c];
}

__global__ void kvsplit_k(const float* __restrict__ KVb, float* __restrict__ Kh,
                          float* __restrict__ Vt)
{
    const int idx = blockIdx.x * blockDim.x + threadIdx.x;
    if (idx >= 16*256*64) return;
    const int zz = idx >> 14, r = idx & 16383, m = r >> 6, d = r & 63;
    const int s = zz >> 3, b = (zz >> 1) & 3, h = zz & 1;
    const float* src = KVb + ((size_t)(s*1024 + b*256 + m)) * 256 + h*64 + d;
    Kh[idx] = src[0] * 0.125f;
    Vt[(size_t)zz*16384 + d*256 + m] = src[128];
}

__global__ void cvec_k(const float* __restrict__ kn, const float* __restrict__ vn,
                       const float* __restrict__ inw, float* __restrict__ cst)
{
    const int t = threadIdx.x;
    const float* w = (t < 128) ? inw + 128*128 + (size_t)t*128
                               : inw + 256*128 + (size_t)(t-128)*128;
    const float* nz = (t < 128) ? kn : vn;
    float s = 0.f;
    #pragma unroll 8
    for (int j = 0; j < 128; ++j) s += nz[j] * w[j];
    cst[t] = s;
}

__global__ void combine_k(const float* __restrict__ QKV, const float* __restrict__ K1,
                          const float* __restrict__ V1, const float* __restrict__ CST,
                          float* __restrict__ OB)
{
    const int n = blockIdx.x, c = threadIdx.x;
    const float* qrow = QKV + (size_t)n * 384;
    const float qp  = qrow[c];
    const float kp0 = qrow[128 + c] + CST[c];
    const float kp1 = K1[(size_t)n * 128 + c];
    float s0 = qp * kp0, s1 = qp * kp1;
    #pragma unroll
    for (int o = 8; o; o >>= 1) {
        s0 += __shfl_xor_sync(0xffffffffu, s0, o, 16);
        s1 += __shfl_xor_sync(0xffffffffu, s1, o, 16);
    }
    s0 *= 0.25f; s1 *= 0.25f;
    const float m = fmaxf(s0, s1);
    const float e0 = __expf(s0 - m), e1 = __expf(s1 - m);
    const float inv = 1.0f / (e0 + e1);
    const float vp0 = qrow[256 + c] + CST[128 + c];
    const float vp1 = V1[(size_t)n * 128 + c];
    OB[(size_t)n * 128 + c] = e0 * inv * vp0 + e1 * inv * vp1;
}

extern "C" void kernel_launch(void* const* d_in, const int* in_sizes, int n_in,
                              void* d_out, int out_size)
{
    const float* x0        = (const float*)d_in[0];
    const float* x1        = (const float*)d_in[1];
    const float* Wq        = (const float*)d_in[2];
    const float* bq        = (const float*)d_in[3];
    const float* Wkv       = (const float*)d_in[4];
    const float* bkv       = (const float*)d_in[5];
    const float* sr_w      = (const float*)d_in[6];
    const float* sr_b      = (const float*)d_in[7];
    const float* ln0_g     = (const float*)d_in[8];
    const float* ln0_b     = (const float*)d_in[9];
    const float* ln1_g     = (const float*)d_in[10];
    const float* ln1_b     = (const float*)d_in[11];
    const float* ca01_in_w = (const float*)d_in[12];
    const float* ca01_in_b = (const float*)d_in[13];
    const float* ca01_out_w= (const float*)d_in[14];
    const float* ca01_out_b= (const float*)d_in[15];
    const float* ca10_in_w = (const float*)d_in[16];
    const float* ca10_in_b = (const float*)d_in[17];
    const float* ca10_out_w= (const float*)d_in[18];
    const float* ca10_out_b= (const float*)d_in[19];
    const float* rj_w1     = (const float*)d_in[20];
    const float* rj_b1     = (const float*)d_in[21];
    const float* rj_w2     = (const float*)d_in[22];
    const float* rj_b2     = (const float*)d_in[23];
    const float* k_noise   = (const float*)d_in[24];
    const float* v_noise   = (const float*)d_in[25];
    const float* proj_w    = (const float*)d_in[26];
    const float* proj_b    = (const float*)d_in[27];

    float* P = nullptr;
    cudaGetSymbolAddress((void**)&P, g_pool);
    float *XA0=P+OFF_XA0, *XA1=P+OFF_XA1, *Q=P+OFF_Q, *PART=P+OFF_PART;
    float *WC=P+OFF_WC, *XILN=P+OFF_XILN, *KVB=P+OFF_KVB, *KH=P+OFF_KH, *VHT=P+OFF_VHT;
    float *HB=P+OFF_HB, *SB=P+OFF_SB, *QKVB=P+OFF_QKV, *K1=P+OFF_K1;
    float *V1=P+OFF_V1, *OB=P+OFF_OB, *N0=P+OFF_N0, *N1=P+OFF_N1, *CST=P+OFF_CST;

    constexpr int SM_128_128 = 2 * (128+128) * 36 * 4;   // 73728
    constexpr int SM_FLASH   = FP_TOT * 4;               // 220160
    constexpr int SM_QKV     = (128*132 + 2*128*36) * 4; // 104448
    cudaFuncSetAttribute(tgemm_k<128,128,4,5,0,0>, cudaFuncAttributeMaxDynamicSharedMemorySize, SM_128_128);
    cudaFuncSetAttribute(tgemm_k<128,128,8,7,4,0>, cudaFuncAttributeMaxDynamicSharedMemorySize, SM_128_128);
    cudaFuncSetAttribute(tgemm_k<128,128,4,0,0,0>, cudaFuncAttributeMaxDynamicSharedMemorySize, SM_128_128);
    cudaFuncSetAttribute(tgemm_k<128,128,8,6,1,0>, cudaFuncAttributeMaxDynamicSharedMemorySize, SM_128_128);
    cudaFuncSetAttribute(tgemm_k<128,128,4,0,0,1>, cudaFuncAttributeMaxDynamicSharedMemorySize, SM_128_128);
    cudaFuncSetAttribute(tgemm_k<128,128,4,2,0,0>, cudaFuncAttributeMaxDynamicSharedMemorySize, SM_128_128);
    cudaFuncSetAttribute(tgemm_k<128,128,4,0,2,0>, cudaFuncAttributeMaxDynamicSharedMemorySize, SM_128_128);
    cudaFuncSetAttribute(flashsr_k, cudaFuncAttributeMaxDynamicSharedMemorySize, SM_FLASH);
    cudaFuncSetAttribute(qkv_k,     cudaFuncAttributeMaxDynamicSharedMemorySize, SM_QKV);

    wconv_k<<<4096, 256>>>(sr_w, WC);

    // q projections, both streams
    tgemm_k<128,128,4,5,0,0><<<dim3(512,1,2), 256, SM_128_128>>>(
        x0, x1, Wq, bq, nullptr, Q, 128, 128, 128, 0, SZ);

    // conv GEMM direct from x, z = stream*32 + ksplit
    tgemm_k<128,128,8,7,4,0><<<dim3(8,1,64), 256, SM_128_128>>>(
        x0, x1, WC, nullptr, nullptr, PART, 8192, 8192, 128, 0, (size_t)BMR*CD);
    convred_ln_k<<<2048, 128>>>(PART, sr_b, ln0_g, ln0_b, ln1_g, ln1_b, XILN);

    // kv projection (2048 rows x 256 cols)
    tgemm_k<128,128,4,0,0,0><<<dim3(16,2,1), 256, SM_128_128>>>(
        XILN, nullptr, Wkv, bkv, nullptr, KVB, 128, 128, 256, 0, 0);
    kvsplit_k<<<1024, 256>>>(KVB, KH, VHT);

    // flash SR attention (scores + softmax + PV fused)
    flashsr_k<<<dim3(256, 16), 256, SM_FLASH>>>(Q, KH, VHT, P /*XA0 base*/);

    // judger: h (concat, gelu) then s (fused softmax), both streams
    tgemm_k<128,128,8,6,1,0><<<dim3(512,1,2), 256, SM_128_128>>>(
        XA0, XA1, rj_w1, rj_b1, nullptr, HB, 128, 256, 128, 0, SZ);
    tgemm_k<128,128,4,0,0,1><<<dim3(512,1,2), 256, SM_128_128>>>(
        HB, nullptr, rj_w2, rj_b2, nullptr, SB, 128, 128, 128, SZ, SZ);

    // mha2 per stream
    for (int s = 0; s < 2; ++s) {
        const float* A  = s ? XA1 : XA0;
        const float* Bx = s ? XA0 : XA1;
        const float* inw = s ? ca10_in_w : ca01_in_w;
        const float* inb = s ? ca10_in_b : ca01_in_b;
        const float* ow  = s ? ca10_out_w : ca01_out_w;
        const float* ob  = s ? ca10_out_b : ca01_out_b;
        float* Nbuf = s ? N1 : N0;
        cvec_k<<<1, 256>>>(k_noise + s*128, v_noise + s*128, inw, CST);
        qkv_k<<<512, 256, SM_QKV>>>(A, inw, inb, QKVB);
        tgemm_k<128,128,4,2,0,0><<<dim3(512,1,1), 256, SM_128_128>>>(
            A, SB + s*SZ, inw + 128*128, inb + 128, nullptr, K1, 128, 128, 128, 0, 0);
        tgemm_k<128,128,4,0,0,0><<<dim3(512,1,1), 256, SM_128_128>>>(
            Bx, nullptr, inw + 256*128, inb + 256, nullptr, V1, 128, 128, 128, 0, 0);
        combine_k<<<65536, 128>>>(QKVB, K1, V1, CST, OB);
        tgemm_k<128,128,4,0,2,0><<<dim3(512,1,1), 256, SM_128_128>>>(
            OB, nullptr, ow, ob, A, Nbuf, 128, 128, 128, 0, 0);
    }

    // final projection, both streams
    float* out = (float*)d_out;
    tgemm_k<128,128,4,0,0,0><<<dim3(512,1,2), 256, SM_128_128>>>(
        N0, nullptr, proj_w, proj_b, nullptr, out, 128, 128, 128, SZ, SZ);
}